// round 16
// baseline (speedup 1.0000x reference)
#include <cuda_runtime.h>

// Scratch (device globals — no runtime allocation allowed)
__device__ float g_part   [4 * 64 * 1024];  // partial column sums of v (64 chunks of 16 rows)
__device__ float g_rowpart[32 * 4 * 1024];  // 32-way split-K partials of vsum @ Wv
__device__ float g_wosum  [64 * 1024];      // WoSum[d][m] = sum_j Wo[j*64+d][m]
__device__ float g_outrows[64 * 1024];      // 16 distinct out rows per batch
__device__ unsigned int g_fc, g_fw, g_f2, g_f3, g_done;  // phase counters

static __device__ __forceinline__ void f4add(float4& a, const float4& b) {
    a.x += b.x; a.y += b.y; a.z += b.z; a.w += b.w;
}

static __device__ __forceinline__ void signal(unsigned int* f) {
    __threadfence();
    __syncthreads();
    if (threadIdx.x == 0) atomicAdd(f, 1u);
}

// Contention-safe wait: volatile load poll + nanosleep (no atomics).
static __device__ __forceinline__ void wait_flag(unsigned int* f, unsigned int tgt,
                                                 unsigned int ns) {
    if (threadIdx.x == 0) {
        while (*(volatile unsigned int*)f < tgt) __nanosleep(ns);
    }
    __syncthreads();
    __threadfence();
}

// ---------------------------------------------------------------------------
// ONE kernel (2560 blocks, 34KB smem -> 6/SM -> 888 wave-1 slots):
//   [0,256)     colsum of v (16-row chunks)                  -> g_fc (256)
//   [256,320)   wosum of Wo                                  -> g_fw (64)
//   [320,448)   vwv: stage Wv chunk to smem BEFORE fc wait   -> g_f2 (128)
//   [448,512)   outrows (wait fw -> ws; wait f2 -> rs; GEMM) -> g_f3 (64)
//   [512,2560)  residual+LN: preload q/gamma/beta, wait f3, finish.
// All 512 worker blocks are wave-1 resident (lowest bids) -> deadlock-free.
// Last LN block resets all counters for the next graph replay.
// ---------------------------------------------------------------------------
__global__ __launch_bounds__(256) void fused_kernel(const float* __restrict__ v,
                                                    const float* __restrict__ Wo,
                                                    const float* __restrict__ Wv,
                                                    const float* __restrict__ q,
                                                    const float* __restrict__ gamma,
                                                    const float* __restrict__ beta,
                                                    float* __restrict__ part,
                                                    float* __restrict__ wosum,
                                                    float* __restrict__ rowpart,
                                                    float* __restrict__ outrows,
                                                    float* __restrict__ out) {
    __shared__ float smem_buf[64 * 128 + 8 * 64];   // 34 KB union
    const int bx = blockIdx.x;
    const int t  = threadIdx.x;

    if (bx < 256) {
        // ---- colsum of v: 16-row chunk ----
        const int s = bx >> 2, b = bx & 3;
        const float4* p = (const float4*)(v + ((size_t)(b * 1024 + s * 16)) * 1024) + t;
        float4 a0 = make_float4(0.f, 0.f, 0.f, 0.f);
        float4 a1 = make_float4(0.f, 0.f, 0.f, 0.f);
#pragma unroll
        for (int i = 0; i < 16; i += 2) {
            float4 x = p[(size_t)i * 256];
            float4 y = p[(size_t)(i + 1) * 256];
            f4add(a0, x);
            f4add(a1, y);
        }
        f4add(a0, a1);
        ((float4*)(part + (size_t)(b * 64 + s) * 1024))[t] = a0;
        signal(&g_fc);
    } else if (bx < 320) {
        // ---- wosum ----
        const int d = bx - 256;      // 0..63
        const float4* src = (const float4*)(Wo + (size_t)d * 1024) + t;
        float4 a0 = make_float4(0.f, 0.f, 0.f, 0.f);
        float4 a1 = make_float4(0.f, 0.f, 0.f, 0.f);
        float4 a2 = make_float4(0.f, 0.f, 0.f, 0.f);
        float4 a3 = make_float4(0.f, 0.f, 0.f, 0.f);
#pragma unroll
        for (int j = 0; j < 16; j += 4) {
            float4 x0 = src[(size_t)(j + 0) * 64 * 256];
            float4 x1 = src[(size_t)(j + 1) * 64 * 256];
            float4 x2 = src[(size_t)(j + 2) * 64 * 256];
            float4 x3 = src[(size_t)(j + 3) * 64 * 256];
            f4add(a0, x0); f4add(a1, x1); f4add(a2, x2); f4add(a3, x3);
        }
        f4add(a0, a1); f4add(a2, a3); f4add(a0, a2);
        ((float4*)(wosum + (size_t)d * 1024))[t] = a0;
        signal(&g_fw);
    } else if (bx < 448) {
        // ---- vwv: kc = 32 k's, oc = 256 o's; Wv staged before the wait ----
        float* wvs = smem_buf;             // [32 kk][256 o] = 32 KB
        float* vs  = smem_buf + 8192;      // [4 b][32 kk]
        const int r = bx - 320, oc = r & 3, kc = r >> 2;  // kc 0..31
        const int k0 = kc * 32, o0 = oc * 256;

        {
            const float4* wv4 = (const float4*)Wv;
#pragma unroll
            for (int it = 0; it < 8; ++it) {
                int idx = t + it * 256;            // 0..2047
                int kk = idx >> 6, o4 = idx & 63;
                ((float4*)wvs)[kk * 64 + o4] = wv4[(size_t)(k0 + kk) * 256 + oc * 64 + o4];
            }
        }

        wait_flag(&g_fc, 256u, 32u);

        if (t < 128) {
            const int b = t >> 5, kk = t & 31;
            const float* pp = part + (size_t)(b * 64) * 1024 + k0 + kk;
            float acc = 0.f;
            float buf[8];
#pragma unroll
            for (int g = 0; g < 8; ++g) {
#pragma unroll
                for (int i = 0; i < 8; ++i) buf[i] = pp[(size_t)(g * 8 + i) * 1024];
#pragma unroll
                for (int i = 0; i < 8; ++i) acc += buf[i];
            }
            vs[b * 32 + kk] = acc;
        }
        __syncthreads();

        const int o = o0 + t;
        float a0 = 0.f, a1 = 0.f, a2 = 0.f, a3 = 0.f;
#pragma unroll
        for (int kk = 0; kk < 32; ++kk) {
            float w = wvs[kk * 256 + t];
            a0 = fmaf(vs[0 * 32 + kk], w, a0);
            a1 = fmaf(vs[1 * 32 + kk], w, a1);
            a2 = fmaf(vs[2 * 32 + kk], w, a2);
            a3 = fmaf(vs[3 * 32 + kk], w, a3);
        }
        float* rp = rowpart + (size_t)kc * 4096;
        rp[0 * 1024 + o] = a0;
        rp[1 * 1024 + o] = a1;
        rp[2 * 1024 + o] = a2;
        rp[3 * 1024 + o] = a3;
        signal(&g_f2);
    } else if (bx < 512) {
        // ---- outrows consumer ----
        float4* ws = (float4*)smem_buf;              // [64][32] float4
        float*  rs = smem_buf + 64 * 128;            // [8][64]
        const int r = bx - 448;
        const int mc = r & 7, bng = r >> 3;

        wait_flag(&g_fw, 64u, 32u);
#pragma unroll
        for (int it = 0; it < 8; ++it) {
            int idx = t + it * 256;            // 0..2047
            int d = idx >> 5, m4 = idx & 31;
            ws[d * 32 + m4] = *((const float4*)(wosum + (size_t)d * 1024 + mc * 128) + m4);
        }

        wait_flag(&g_f2, 128u, 32u);
#pragma unroll
        for (int it = 0; it < 2; ++it) {
            int idx = t + it * 256;            // 0..511
            int bnl = idx >> 6, d = idx & 63;
            int bn = bng * 8 + bnl;
            int b = bn >> 4, o = (bn & 15) * 64 + d;
            const float* rp = rowpart + (size_t)b * 1024 + o;
            float acc = 0.f;
            float buf[8];
#pragma unroll
            for (int g = 0; g < 4; ++g) {
#pragma unroll
                for (int i = 0; i < 8; ++i) buf[i] = rp[(size_t)((g * 8 + i) * 4) * 1024];
#pragma unroll
                for (int i = 0; i < 8; ++i) acc += buf[i];
            }
            rs[bnl * 64 + d] = acc;
        }
        __syncthreads();

        const int bnl = t >> 5, m4 = t & 31;   // warp = bnl -> rs broadcast
        float4 acc = make_float4(0.f, 0.f, 0.f, 0.f);
#pragma unroll
        for (int d = 0; d < 64; ++d) {
            float a = rs[bnl * 64 + d];
            float4 w = ws[d * 32 + m4];
            acc.x = fmaf(a, w.x, acc.x);
            acc.y = fmaf(a, w.y, acc.y);
            acc.z = fmaf(a, w.z, acc.z);
            acc.w = fmaf(a, w.w, acc.w);
        }
        const int bn = bng * 8 + bnl;
        *((float4*)(outrows + (size_t)bn * 1024 + mc * 128) + m4) = acc;
        signal(&g_f3);
    } else {
        // ---- residual + LayerNorm (2 rows/block, 4 warps/row) ----
        float2* psum = (float2*)smem_buf;
        const int lnb  = bx - 512;                         // 0..2047
        const int warp = t >> 5, lane = t & 31;
        const int rloc = warp >> 2, qtr = warp & 3;
        const int row  = lnb * 2 + rloc;                   // 0..4095
        const int bn   = (row >> 10) * 16 + ((row & 1023) >> 6);
        const int f4   = qtr * 64 + lane;

        // Preload q/gamma/beta NOW — overlaps pm phases on other SMs.
        const float4* rp = (const float4*)(q + (size_t)row * 1024) + f4;
        float4 r0 = rp[0], r1 = rp[32];
        const float4* gp = (const float4*)gamma + f4;
        const float4* bp = (const float4*)beta  + f4;
        float4 g0 = gp[0], g1 = gp[32];
        float4 b0 = bp[0], b1 = bp[32];

        wait_flag(&g_f3, 64u, 256u);

        const float4* yp = (const float4*)(outrows + (size_t)bn * 1024) + f4;
        float4 y0 = yp[0], y1 = yp[32];
        float4 x0 = make_float4(y0.x + r0.x, y0.y + r0.y, y0.z + r0.z, y0.w + r0.w);
        float4 x1 = make_float4(y1.x + r1.x, y1.y + r1.y, y1.z + r1.z, y1.w + r1.w);

        float s  = x0.x + x0.y + x0.z + x0.w + x1.x + x1.y + x1.z + x1.w;
        float sq = x0.x * x0.x + x0.y * x0.y + x0.z * x0.z + x0.w * x0.w
                 + x1.x * x1.x + x1.y * x1.y + x1.z * x1.z + x1.w * x1.w;
#pragma unroll
        for (int off = 16; off >= 1; off >>= 1) {
            s  += __shfl_xor_sync(0xffffffffu, s,  off);
            sq += __shfl_xor_sync(0xffffffffu, sq, off);
        }
        if (lane == 0) psum[warp] = make_float2(s, sq);
        __syncthreads();
        {
            float2 a = psum[rloc * 4 + 0], b = psum[rloc * 4 + 1];
            float2 c = psum[rloc * 4 + 2], d = psum[rloc * 4 + 3];
            s  = a.x + b.x + c.x + d.x;
            sq = a.y + b.y + c.y + d.y;
        }
        const float mean = s * (1.f / 1024.f);
        const float inv  = rsqrtf(sq * (1.f / 1024.f) - mean * mean + 1e-6f);

        float4* op = (float4*)(out + (size_t)row * 1024) + f4;
        op[0]  = make_float4((x0.x - mean) * inv * g0.x + b0.x,
                             (x0.y - mean) * inv * g0.y + b0.y,
                             (x0.z - mean) * inv * g0.z + b0.z,
                             (x0.w - mean) * inv * g0.w + b0.w);
        op[32] = make_float4((x1.x - mean) * inv * g1.x + b1.x,
                             (x1.y - mean) * inv * g1.y + b1.y,
                             (x1.z - mean) * inv * g1.z + b1.z,
                             (x1.w - mean) * inv * g1.w + b1.w);

        // completion count; last LN block resets flags for the next replay
        __syncthreads();
        if (t == 0) {
            __threadfence();
            unsigned int old = atomicAdd(&g_done, 1u);
            if (old == 2047u) {
                g_fc = 0u; g_fw = 0u; g_f2 = 0u; g_f3 = 0u; g_done = 0u;
                __threadfence();
            }
        }
    }
}

// ---------------------------------------------------------------------------
extern "C" void kernel_launch(void* const* d_in, const int* in_sizes, int n_in,
                              void* d_out, int out_size) {
    (void)in_sizes; (void)n_in; (void)out_size;
    const float* q     = (const float*)d_in[0];
    const float* v     = (const float*)d_in[2];
    const float* Wv    = (const float*)d_in[6];
    const float* Wo    = (const float*)d_in[7];
    const float* gamma = (const float*)d_in[8];
    const float* beta  = (const float*)d_in[9];
    float* out = (float*)d_out;

    float *part, *rowpart, *wosum, *outrows;
    cudaGetSymbolAddress((void**)&part,    g_part);
    cudaGetSymbolAddress((void**)&rowpart, g_rowpart);
    cudaGetSymbolAddress((void**)&wosum,   g_wosum);
    cudaGetSymbolAddress((void**)&outrows, g_outrows);

    fused_kernel<<<2560, 256>>>(v, Wo, Wv, q, gamma, beta,
                                part, wosum, rowpart, outrows, out);
}

// round 17
// speedup vs baseline: 1.1825x; 1.1825x over previous
#include <cuda_runtime.h>

// Scratch (device globals — no runtime allocation allowed)
__device__ float g_part   [4 * 64 * 1024];  // partial column sums of v (64 chunks of 16 rows)
__device__ float g_rowpart[32 * 4 * 1024];  // 32-way split-K partials of vsum @ Wv
__device__ float g_wosum  [64 * 1024];      // WoSum[d][m] = sum_j Wo[j*64+d][m]
__device__ float g_outrows[64 * 1024];      // 16 distinct out rows per batch
__device__ unsigned int g_fc, g_fw, g_f2;   // phase counters (reset by ln after sync)

static __device__ __forceinline__ void f4add(float4& a, const float4& b) {
    a.x += b.x; a.y += b.y; a.z += b.z; a.w += b.w;
}

static __device__ __forceinline__ void signal(unsigned int* f) {
    __threadfence();
    __syncthreads();
    if (threadIdx.x == 0) atomicAdd(f, 1u);
}

static __device__ __forceinline__ void spin_until(unsigned int* f, unsigned int tgt) {
    if (threadIdx.x == 0) {
        while (atomicAdd(f, 0u) < tgt) { }
    }
    __syncthreads();
    __threadfence();
}

// ---------------------------------------------------------------------------
// Node 1 (512 blocks; exact R15 layout — proven 20.96 us):
//   [0,256)   colsum of v (16-row chunks)                    -> g_fc (256)
//   [256,320) wosum of Wo                                    -> g_fw (64)
//   [320,448) vwv: stage Wv chunk to smem BEFORE fc spin     -> g_f2 (128)
//   [448,512) outrows (wait fw -> ws; wait f2 -> rs; GEMM)
// Every block triggers PDL completion at entry so the ln grid can launch
// early and overlap its q-preload with this kernel.
// ---------------------------------------------------------------------------
__global__ __launch_bounds__(256) void pm_kernel(const float* __restrict__ v,
                                                 const float* __restrict__ Wo,
                                                 const float* __restrict__ Wv,
                                                 float* __restrict__ part,
                                                 float* __restrict__ wosum,
                                                 float* __restrict__ rowpart,
                                                 float* __restrict__ outrows) {
    __shared__ float smem_buf[64 * 128 + 8 * 64];   // 34 KB union
    const int bx = blockIdx.x;
    const int t  = threadIdx.x;

    cudaTriggerProgrammaticLaunchCompletion();

    if (bx < 256) {
        // ---- colsum of v: 16-row chunk ----
        const int s = bx >> 2, b = bx & 3;
        const float4* p = (const float4*)(v + ((size_t)(b * 1024 + s * 16)) * 1024) + t;
        float4 a0 = make_float4(0.f, 0.f, 0.f, 0.f);
        float4 a1 = make_float4(0.f, 0.f, 0.f, 0.f);
#pragma unroll
        for (int i = 0; i < 16; i += 2) {
            float4 x = p[(size_t)i * 256];
            float4 y = p[(size_t)(i + 1) * 256];
            f4add(a0, x);
            f4add(a1, y);
        }
        f4add(a0, a1);
        ((float4*)(part + (size_t)(b * 64 + s) * 1024))[t] = a0;
        signal(&g_fc);
    } else if (bx < 320) {
        // ---- wosum ----
        const int d = bx - 256;      // 0..63
        const float4* src = (const float4*)(Wo + (size_t)d * 1024) + t;
        float4 a0 = make_float4(0.f, 0.f, 0.f, 0.f);
        float4 a1 = make_float4(0.f, 0.f, 0.f, 0.f);
        float4 a2 = make_float4(0.f, 0.f, 0.f, 0.f);
        float4 a3 = make_float4(0.f, 0.f, 0.f, 0.f);
#pragma unroll
        for (int j = 0; j < 16; j += 4) {
            float4 x0 = src[(size_t)(j + 0) * 64 * 256];
            float4 x1 = src[(size_t)(j + 1) * 64 * 256];
            float4 x2 = src[(size_t)(j + 2) * 64 * 256];
            float4 x3 = src[(size_t)(j + 3) * 64 * 256];
            f4add(a0, x0); f4add(a1, x1); f4add(a2, x2); f4add(a3, x3);
        }
        f4add(a0, a1); f4add(a2, a3); f4add(a0, a2);
        ((float4*)(wosum + (size_t)d * 1024))[t] = a0;
        signal(&g_fw);
    } else if (bx < 448) {
        // ---- vwv: kc = 32 k's, oc = 256 o's; Wv staged before the wait ----
        float* wvs = smem_buf;             // [32 kk][256 o] = 32 KB
        float* vs  = smem_buf + 8192;      // [4 b][32 kk]
        const int r = bx - 320, oc = r & 3, kc = r >> 2;  // kc 0..31
        const int k0 = kc * 32, o0 = oc * 256;

        {
            const float4* wv4 = (const float4*)Wv;
#pragma unroll
            for (int it = 0; it < 8; ++it) {
                int idx = t + it * 256;            // 0..2047
                int kk = idx >> 6, o4 = idx & 63;
                ((float4*)wvs)[kk * 64 + o4] = wv4[(size_t)(k0 + kk) * 256 + oc * 64 + o4];
            }
        }

        spin_until(&g_fc, 256u);

        if (t < 128) {
            const int b = t >> 5, kk = t & 31;
            const float* pp = part + (size_t)(b * 64) * 1024 + k0 + kk;
            float acc = 0.f;
            float buf[8];
#pragma unroll
            for (int g = 0; g < 8; ++g) {
#pragma unroll
                for (int i = 0; i < 8; ++i) buf[i] = pp[(size_t)(g * 8 + i) * 1024];
#pragma unroll
                for (int i = 0; i < 8; ++i) acc += buf[i];
            }
            vs[b * 32 + kk] = acc;
        }
        __syncthreads();

        const int o = o0 + t;
        float a0 = 0.f, a1 = 0.f, a2 = 0.f, a3 = 0.f;
#pragma unroll
        for (int kk = 0; kk < 32; ++kk) {
            float w = wvs[kk * 256 + t];
            a0 = fmaf(vs[0 * 32 + kk], w, a0);
            a1 = fmaf(vs[1 * 32 + kk], w, a1);
            a2 = fmaf(vs[2 * 32 + kk], w, a2);
            a3 = fmaf(vs[3 * 32 + kk], w, a3);
        }
        float* rp = rowpart + (size_t)kc * 4096;
        rp[0 * 1024 + o] = a0;
        rp[1 * 1024 + o] = a1;
        rp[2 * 1024 + o] = a2;
        rp[3 * 1024 + o] = a3;
        signal(&g_f2);
    } else {
        // ---- outrows consumer ----
        float4* ws = (float4*)smem_buf;              // [64][32] float4
        float*  rs = smem_buf + 64 * 128;            // [8][64]
        const int r = bx - 448;
        const int mc = r & 7, bng = r >> 3;

        spin_until(&g_fw, 64u);
#pragma unroll
        for (int it = 0; it < 8; ++it) {
            int idx = t + it * 256;            // 0..2047
            int d = idx >> 5, m4 = idx & 31;
            ws[d * 32 + m4] = *((const float4*)(wosum + (size_t)d * 1024 + mc * 128) + m4);
        }

        spin_until(&g_f2, 128u);
#pragma unroll
        for (int it = 0; it < 2; ++it) {
            int idx = t + it * 256;            // 0..511
            int bnl = idx >> 6, d = idx & 63;
            int bn = bng * 8 + bnl;
            int b = bn >> 4, o = (bn & 15) * 64 + d;
            const float* rp = rowpart + (size_t)b * 1024 + o;
            float acc = 0.f;
            float buf[8];
#pragma unroll
            for (int g = 0; g < 4; ++g) {
#pragma unroll
                for (int i = 0; i < 8; ++i) buf[i] = rp[(size_t)((g * 8 + i) * 4) * 1024];
#pragma unroll
                for (int i = 0; i < 8; ++i) acc += buf[i];
            }
            rs[bnl * 64 + d] = acc;
        }
        __syncthreads();

        const int bnl = t >> 5, m4 = t & 31;   // warp = bnl -> rs broadcast
        float4 acc = make_float4(0.f, 0.f, 0.f, 0.f);
#pragma unroll
        for (int d = 0; d < 64; ++d) {
            float a = rs[bnl * 64 + d];
            float4 w = ws[d * 32 + m4];
            acc.x = fmaf(a, w.x, acc.x);
            acc.y = fmaf(a, w.y, acc.y);
            acc.z = fmaf(a, w.z, acc.z);
            acc.w = fmaf(a, w.w, acc.w);
        }
        const int bn = bng * 8 + bnl;
        *((float4*)(outrows + (size_t)bn * 1024 + mc * 128) + m4) = acc;
    }
}

// ---------------------------------------------------------------------------
// Node 2 (PDL secondary): residual add + LayerNorm, FOUR WARPS PER ROW.
// Launched with programmatic stream serialization: starts while pm runs,
// preloads q/gamma/beta into registers, then cudaGridDependencySynchronize()
// waits for pm's full completion before touching outrows.
// Block 0 resets the phase counters AFTER the sync (pm is done by then).
// ---------------------------------------------------------------------------
__global__ __launch_bounds__(256) void ln_kernel(const float* __restrict__ outrows,
                                                 const float* __restrict__ q,
                                                 const float* __restrict__ gamma,
                                                 const float* __restrict__ beta,
                                                 float* __restrict__ out) {
    __shared__ float2 psum[8];
    const int warp = threadIdx.x >> 5, lane = threadIdx.x & 31;
    const int rloc = warp >> 2, qtr = warp & 3;
    const int row  = blockIdx.x * 2 + rloc;            // 0..4095
    const int bn   = (row >> 10) * 16 + ((row & 1023) >> 6);
    const int f4   = qtr * 64 + lane;                  // float4 index base

    // Preload independent inputs BEFORE the dependency sync (overlaps pm).
    const float4* rp = (const float4*)(q + (size_t)row * 1024) + f4;
    float4 r0 = rp[0], r1 = rp[32];
    const float4* gp = (const float4*)gamma + f4;
    const float4* bp = (const float4*)beta  + f4;
    float4 g0 = gp[0], g1 = gp[32];
    float4 b0 = bp[0], b1 = bp[32];

    cudaGridDependencySynchronize();

    if (blockIdx.x == 0 && threadIdx.x == 0) {
        g_fc = 0u; g_fw = 0u; g_f2 = 0u;   // safe: pm grid fully complete
    }

    const float4* yp = (const float4*)(outrows + (size_t)bn * 1024) + f4;
    float4 y0 = yp[0], y1 = yp[32];
    float4 x0 = make_float4(y0.x + r0.x, y0.y + r0.y, y0.z + r0.z, y0.w + r0.w);
    float4 x1 = make_float4(y1.x + r1.x, y1.y + r1.y, y1.z + r1.z, y1.w + r1.w);

    float s  = x0.x + x0.y + x0.z + x0.w + x1.x + x1.y + x1.z + x1.w;
    float sq = x0.x * x0.x + x0.y * x0.y + x0.z * x0.z + x0.w * x0.w
             + x1.x * x1.x + x1.y * x1.y + x1.z * x1.z + x1.w * x1.w;
#pragma unroll
    for (int off = 16; off >= 1; off >>= 1) {
        s  += __shfl_xor_sync(0xffffffffu, s,  off);
        sq += __shfl_xor_sync(0xffffffffu, sq, off);
    }
    if (lane == 0) psum[warp] = make_float2(s, sq);
    __syncthreads();
    {
        float2 a = psum[rloc * 4 + 0], b = psum[rloc * 4 + 1];
        float2 c = psum[rloc * 4 + 2], d = psum[rloc * 4 + 3];
        s  = a.x + b.x + c.x + d.x;
        sq = a.y + b.y + c.y + d.y;
    }
    const float mean = s * (1.f / 1024.f);
    const float inv  = rsqrtf(sq * (1.f / 1024.f) - mean * mean + 1e-6f);

    float4* op = (float4*)(out + (size_t)row * 1024) + f4;
    op[0]  = make_float4((x0.x - mean) * inv * g0.x + b0.x,
                         (x0.y - mean) * inv * g0.y + b0.y,
                         (x0.z - mean) * inv * g0.z + b0.z,
                         (x0.w - mean) * inv * g0.w + b0.w);
    op[32] = make_float4((x1.x - mean) * inv * g1.x + b1.x,
                         (x1.y - mean) * inv * g1.y + b1.y,
                         (x1.z - mean) * inv * g1.z + b1.z,
                         (x1.w - mean) * inv * g1.w + b1.w);
}

// ---------------------------------------------------------------------------
extern "C" void kernel_launch(void* const* d_in, const int* in_sizes, int n_in,
                              void* d_out, int out_size) {
    (void)in_sizes; (void)n_in; (void)out_size;
    const float* q     = (const float*)d_in[0];
    const float* v     = (const float*)d_in[2];
    const float* Wv    = (const float*)d_in[6];
    const float* Wo    = (const float*)d_in[7];
    const float* gamma = (const float*)d_in[8];
    const float* beta  = (const float*)d_in[9];
    float* out = (float*)d_out;

    float *part, *rowpart, *wosum, *outrows;
    cudaGetSymbolAddress((void**)&part,    g_part);
    cudaGetSymbolAddress((void**)&rowpart, g_rowpart);
    cudaGetSymbolAddress((void**)&wosum,   g_wosum);
    cudaGetSymbolAddress((void**)&outrows, g_outrows);

    pm_kernel<<<512, 256>>>(v, Wo, Wv, part, wosum, rowpart, outrows);

    // ln with programmatic dependent launch: overlaps its q preload with pm.
    cudaLaunchConfig_t cfg = {};
    cfg.gridDim  = dim3(2048, 1, 1);
    cfg.blockDim = dim3(256, 1, 1);
    cfg.dynamicSmemBytes = 0;
    cfg.stream = 0;
    cudaLaunchAttribute attr[1];
    attr[0].id = cudaLaunchAttributeProgrammaticStreamSerialization;
    attr[0].val.programmaticStreamSerializationAllowed = 1;
    cfg.attrs = attr;
    cfg.numAttrs = 1;
    cudaLaunchKernelEx(&cfg, ln_kernel, outrows, q, gamma, beta, out);
}